// round 8
// baseline (speedup 1.0000x reference)
#include <cuda_runtime.h>
#include <cuda_bf16.h>
#include <math.h>

typedef unsigned long long ull;

// ---------------- constants ----------------
#define T_LEN 512
#define B_SZ  64
#define E_DIM 256
#define H_DIM 256
#define S_ST  64
#define G4H   1024   // 4*H

// ---------------- device scratch ----------------
__device__ float g_xg[2][T_LEN][B_SZ][G4H];   // precomputed x-gates + bias (chain-step order)
__device__ float g_h[T_LEN * B_SZ][2 * H_DIM]; // BiLSTM features
__device__ float g_sc[T_LEN * B_SZ][S_ST];     // emission scores (incl b_lin)

// ---------------- helpers ----------------
__device__ __forceinline__ ull pk2(float x, float y) {
    ull r; asm("mov.b64 %0, {%1,%2};" : "=l"(r) : "f"(x), "f"(y)); return r;
}
__device__ __forceinline__ void upk2(ull v, float& x, float& y) {
    asm("mov.b64 {%0,%1}, %2;" : "=f"(x), "=f"(y) : "l"(v));
}
__device__ __forceinline__ ull fma2_(ull a, ull b, ull c) {
    ull d; asm("fma.rn.f32x2 %0, %1, %2, %3;" : "=l"(d) : "l"(a), "l"(b), "l"(c)); return d;
}
__device__ __forceinline__ ull add2_(ull a, ull b) {
    ull d; asm("add.rn.f32x2 %0, %1, %2;" : "=l"(d) : "l"(a), "l"(b)); return d;
}
__device__ __forceinline__ unsigned smem_u32(const void* p) {
    unsigned a;
    asm("{ .reg .u64 t; cvta.to.shared.u64 t, %1; cvt.u32.u64 %0, t; }" : "=r"(a) : "l"(p));
    return a;
}
__device__ __forceinline__ unsigned mapa_(unsigned addr, unsigned rank) {
    unsigned r; asm("mapa.shared::cluster.u32 %0, %1, %2;" : "=r"(r) : "r"(addr), "r"(rank));
    return r;
}
#define CLUSTER_SYNC() do { \
    asm volatile("barrier.cluster.arrive.aligned;" ::: "memory"); \
    asm volatile("barrier.cluster.wait.aligned;"   ::: "memory"); \
} while (0)

#define MBAR_INIT(addr, cnt) \
    asm volatile("mbarrier.init.shared.b64 [%0], %1;" :: "r"(addr), "r"(cnt) : "memory")
#define MBAR_INVAL(addr) \
    asm volatile("mbarrier.inval.shared.b64 [%0];" :: "r"(addr) : "memory")
#define MBAR_EXPECT_TX(addr, tx) \
    asm volatile("mbarrier.arrive.expect_tx.shared.b64 _, [%0], %1;" \
                 :: "r"(addr), "r"(tx) : "memory")
#define MBAR_ARRIVE_CLUSTER(raddr) \
    asm volatile("mbarrier.arrive.shared::cluster.b64 _, [%0];" :: "r"(raddr) : "memory")

#define MBAR_WAIT(addr, parity) do { \
    unsigned _mb = (addr); unsigned _ph = (parity); unsigned _done; \
    asm volatile("{\n\t.reg .pred p;\n\t" \
        "mbarrier.try_wait.parity.acquire.cta.shared::cta.b64 p, [%1], %2;\n\t" \
        "selp.b32 %0, 1, 0, p;\n\t}" : "=r"(_done) : "r"(_mb), "r"(_ph) : "memory"); \
    if (!_done) { \
        asm volatile("{\n\t.reg .pred P1;\n\t" \
            "WL_%=:\n\t" \
            "mbarrier.try_wait.parity.acquire.cta.shared::cta.b64 P1, [%0], %1, 0x989680;\n\t" \
            "@P1 bra.uni WD_%=;\n\t" \
            "bra.uni WL_%=;\n\t" \
            "WD_%=:\n\t}" :: "r"(_mb), "r"(_ph) : "memory"); \
    } \
} while (0)

#define BULK_S2S(dst, src, bytes, mbar) \
    asm volatile("cp.async.bulk.shared::cluster.shared::cta.mbarrier::complete_tx::bytes " \
                 "[%0], [%1], %2, [%3];" \
                 :: "r"(dst), "r"(src), "r"(bytes), "r"(mbar) : "memory")

// named barriers (producer/consumer credits)
#define NB_SYNC(id, cnt) \
    asm volatile("bar.sync %0, %1;" :: "r"(id), "r"(cnt) : "memory")
#define NB_ARRIVE(id, cnt) \
    asm volatile("bar.arrive %0, %1;" :: "r"(id), "r"(cnt) : "memory")

__device__ __forceinline__ float sgm(float x) { return 1.0f / (1.0f + expf(-x)); }
__device__ __forceinline__ float tanh_(float x) { return 1.0f - 2.0f / (expf(2.0f * x) + 1.0f); }

// =====================================================================
// Kernel A: x-gates GEMM (R7 version).
// =====================================================================
__global__ void __launch_bounds__(256) kA(
    const int* __restrict__ obs, const float* __restrict__ emb,
    const float* __restrict__ WihF, const float* __restrict__ WihB,
    const float* __restrict__ bihF, const float* __restrict__ bhhF,
    const float* __restrict__ bihB, const float* __restrict__ bhhB)
{
    __shared__ float As[32][132];
    __shared__ float Bs[32][68];
    __shared__ int rowidx[128];

    const int tid = threadIdx.x;
    const int mBase = blockIdx.x * 128;
    const int nTile = blockIdx.y;
    const int dir = nTile >> 4;
    const int nBase = (nTile & 15) * 64;
    const float* W = dir ? WihB : WihF;

    if (tid < 128) rowidx[tid] = obs[mBase + tid];
    __syncthreads();

    const int ty = tid >> 4;
    const int tx = tid & 15;

    ull acc[4][4];
#pragma unroll
    for (int m = 0; m < 4; m++)
#pragma unroll
        for (int j = 0; j < 4; j++) acc[m][j] = 0ull;

    const int arow = tid >> 3, akq = tid & 7;
    const int bn = tid >> 2, bkq = tid & 3;

    float4 pa[4], pb[2];
#pragma unroll
    for (int rr = 0; rr < 4; ++rr)
        pa[rr] = *reinterpret_cast<const float4*>(
            &emb[(size_t)rowidx[arow + rr * 32] * E_DIM + akq * 4]);
#pragma unroll
    for (int hh = 0; hh < 2; ++hh)
        pb[hh] = *reinterpret_cast<const float4*>(
            &W[(size_t)(nBase + bn) * E_DIM + bkq * 8 + hh * 4]);

    for (int kt = 0; kt < 8; ++kt) {
#pragma unroll
        for (int rr = 0; rr < 4; ++rr) {
            int r = arow + rr * 32;
            As[akq * 4 + 0][r] = pa[rr].x; As[akq * 4 + 1][r] = pa[rr].y;
            As[akq * 4 + 2][r] = pa[rr].z; As[akq * 4 + 3][r] = pa[rr].w;
        }
#pragma unroll
        for (int hh = 0; hh < 2; ++hh) {
            Bs[bkq * 8 + hh * 4 + 0][bn] = pb[hh].x; Bs[bkq * 8 + hh * 4 + 1][bn] = pb[hh].y;
            Bs[bkq * 8 + hh * 4 + 2][bn] = pb[hh].z; Bs[bkq * 8 + hh * 4 + 3][bn] = pb[hh].w;
        }
        __syncthreads();

        if (kt < 7) {
            const int kn = (kt + 1) * 32;
#pragma unroll
            for (int rr = 0; rr < 4; ++rr)
                pa[rr] = *reinterpret_cast<const float4*>(
                    &emb[(size_t)rowidx[arow + rr * 32] * E_DIM + kn + akq * 4]);
#pragma unroll
            for (int hh = 0; hh < 2; ++hh)
                pb[hh] = *reinterpret_cast<const float4*>(
                    &W[(size_t)(nBase + bn) * E_DIM + kn + bkq * 8 + hh * 4]);
        }

#pragma unroll 8
        for (int k = 0; k < 32; ++k) {
            float4 a0 = *reinterpret_cast<const float4*>(&As[k][ty * 8]);
            float4 a1 = *reinterpret_cast<const float4*>(&As[k][ty * 8 + 4]);
            float4 b4 = *reinterpret_cast<const float4*>(&Bs[k][tx * 4]);
            ull ap[4] = {pk2(a0.x, a0.y), pk2(a0.z, a0.w), pk2(a1.x, a1.y), pk2(a1.z, a1.w)};
            ull bd[4] = {pk2(b4.x, b4.x), pk2(b4.y, b4.y), pk2(b4.z, b4.z), pk2(b4.w, b4.w)};
#pragma unroll
            for (int m = 0; m < 4; ++m)
#pragma unroll
                for (int j = 0; j < 4; ++j)
                    acc[m][j] = fma2_(ap[m], bd[j], acc[m][j]);
        }
        __syncthreads();
    }

    const int n0 = nBase + tx * 4;
    const float* bi = dir ? bihB : bihF;
    const float* bh = dir ? bhhB : bhhF;
    float bias[4];
#pragma unroll
    for (int j = 0; j < 4; ++j) bias[j] = bi[n0 + j] + bh[n0 + j];
#pragma unroll
    for (int m = 0; m < 4; ++m) {
        float lo[4], hi[4];
#pragma unroll
        for (int j = 0; j < 4; ++j) upk2(acc[m][j], lo[j], hi[j]);
        int mg0 = mBase + ty * 8 + 2 * m;
#pragma unroll
        for (int r = 0; r < 2; ++r) {
            int mg = mg0 + r;
            int t = mg >> 6, b = mg & 63;
            int sIdx = dir ? (T_LEN - 1 - t) : t;
            const float* src = r ? hi : lo;
            float4 o = make_float4(src[0] + bias[0], src[1] + bias[1],
                                   src[2] + bias[2], src[3] + bias[3]);
            *reinterpret_cast<float4*>(&g_xg[dir][sIdx][b][n0]) = o;
        }
    }
}

// =====================================================================
// Kernel B: WARP-SPECIALIZED recurrence.
//   warps 0-7  (tid 0-255):   GEMV producers (Whh in SMEM, gred[2] out)
//   warps 8-15 (tid 256-511): reduce + LSTM cell + DSMEM push + h store
// Two interleaved chains; consumer tail of chain A hides under
// producer GEMV of chain B and vice versa.
// Named barriers: 1,2 = nbCONS[ch] (prod->cons "gred ready")
//                 3,4 = nbPROD[ch] (cons->prod "gred free + h self ok")
//                 5   = intra-producer, 6,7 = intra-consumer.
// =====================================================================
struct SmemB {
    float Wsm[256][128];         // K-major Whh slice         131072 B
    float hbuf[2][2][H_DIM][8];  // [chain][pp][k][batch]      32768 B
    ull   gred[2][2048];         // [chain][(slot*4+c)*64+rp]  32768 B
    float gfull[8][132];         // gates [batch][row(+pad)]    4224 B
    float hstage[2][2][256];     // [chain][pp]                 4096 B
    ull   mb_full[2][2];
    ull   mb_go[2][2];
};

__global__ void __launch_bounds__(512, 1) __cluster_dims__(8, 1, 1) kB(
    const float* __restrict__ WhhF, const float* __restrict__ WhhB,
    const float* __restrict__ h0, const float* __restrict__ c0)
{
    extern __shared__ char smraw[];
    SmemB& sm = *reinterpret_cast<SmemB*>(smraw);

    const int tid = threadIdx.x;
    const int blk = blockIdx.x;
    const int cr = blk & 7;            // cluster rank -> units [32cr,32cr+32)
    const int cid = blk >> 3;          // 0..7
    const int dir = cid >> 2;
    const int bgp = cid & 3;
    const int b0A = bgp * 16;          // chain0 batches; chain1 = +8
    const float* Whh = dir ? WhhB : WhhF;
    const float* xg = &g_xg[dir][0][0][0];

    // ---- load Whh slice into SMEM, K-major (conflict-free stores) ----
    for (int idx = tid; idx < 128 * 64; idx += 512) {
        int j = idx & 127, k4 = idx >> 7;     // j fastest -> STS stride 4B
        int rg = ((j >> 5) << 8) + (cr << 5) + (j & 31);
        const float4 v = *reinterpret_cast<const float4*>(&Whh[(size_t)rg * H_DIM + (k4 << 2)]);
        sm.Wsm[k4 * 4 + 0][j] = v.x; sm.Wsm[k4 * 4 + 1][j] = v.y;
        sm.Wsm[k4 * 4 + 2][j] = v.z; sm.Wsm[k4 * 4 + 3][j] = v.w;
    }
    // ---- init hbuf[ch][0] ----
    for (int idx = tid; idx < 4096; idx += 512) {
        int ch = idx >> 11, r2 = idx & 2047;
        int k = r2 >> 3, bb = r2 & 7;
        sm.hbuf[ch][0][k][bb] = h0[((size_t)dir * B_SZ + b0A + ch * 8 + bb) * H_DIM + k];
    }

    // ---- barrier addresses ----
    unsigned goL[2][2], fullL[2][2], dstL[2][2];
#pragma unroll
    for (int ch = 0; ch < 2; ++ch)
#pragma unroll
        for (int pp = 0; pp < 2; ++pp) {
            goL[ch][pp]   = smem_u32(&sm.mb_go[ch][pp]);
            fullL[ch][pp] = smem_u32(&sm.mb_full[ch][pp]);
            dstL[ch][pp]  = smem_u32(&sm.hbuf[ch][pp][cr * 32][0]);
        }

    if (tid == 0) {
#pragma unroll
        for (int ch = 0; ch < 2; ++ch) {
            MBAR_INIT(fullL[ch][0], 1); MBAR_INIT(fullL[ch][1], 1);
            MBAR_INIT(goL[ch][0], 8);   MBAR_INIT(goL[ch][1], 8);
            MBAR_EXPECT_TX(fullL[ch][1], 7168);   // arm for step-0 pushes
        }
    }
    // consumer cell state
    float c_reg[2] = {0.f, 0.f};
    if (tid >= 256) {
        int ci = tid - 256;
        int u = ci >> 3, bb = ci & 7;
        c_reg[0] = c0[((size_t)dir * B_SZ + b0A + bb) * H_DIM + cr * 32 + u];
        c_reg[1] = c0[((size_t)dir * B_SZ + b0A + 8 + bb) * H_DIM + cr * 32 + u];
    }
    __syncthreads();
    CLUSTER_SYNC();

    if (tid == 0) {
#pragma unroll
        for (int ch = 0; ch < 2; ++ch)
#pragma unroll
            for (int j = 0; j < 8; ++j)
                MBAR_ARRIVE_CLUSTER(mapa_(goL[ch][1], (unsigned)j));
    }

    if (tid < 256) {
        // =================== PRODUCER (GEMV) ===================
        const int c4 = tid >> 6;       // 0..3 : 64-k chunk
        const int rp = tid & 63;       // rows 2rp, 2rp+1
        unsigned phF[2] = {0, 0};

        for (int s = 0; s < T_LEN; ++s) {
            const int p = s & 1;
#pragma unroll
            for (int ch = 0; ch < 2; ++ch) {
                if (s > 0) {
                    NB_SYNC(3 + ch, 512);                    // gred free + h self ok
                    MBAR_WAIT(fullL[ch][p], (phF[ch] >> p) & 1);
                    phF[ch] ^= (1u << p);
                }
                // GEMV over 64 k
                ull aA0 = 0, aA1 = 0, aA2 = 0, aA3 = 0;
                ull aB0 = 0, aB1 = 0, aB2 = 0, aB3 = 0;
                const float* wrow = &sm.Wsm[c4 * 64][2 * rp];
                const ulonglong2* hp2 =
                    reinterpret_cast<const ulonglong2*>(&sm.hbuf[ch][p][c4 * 64][0]);
#pragma unroll 8
                for (int k = 0; k < 64; ++k) {
                    float2 w2 = *reinterpret_cast<const float2*>(wrow + (size_t)k * 128);
                    ulonglong2 hA = hp2[k * 2 + 0];
                    ulonglong2 hB = hp2[k * 2 + 1];
                    ull wa = pk2(w2.x, w2.x);
                    ull wb = pk2(w2.y, w2.y);
                    aA0 = fma2_(wa, hA.x, aA0); aA1 = fma2_(wa, hA.y, aA1);
                    aA2 = fma2_(wa, hB.x, aA2); aA3 = fma2_(wa, hB.y, aA3);
                    aB0 = fma2_(wb, hA.x, aB0); aB1 = fma2_(wb, hA.y, aB1);
                    aB2 = fma2_(wb, hB.x, aB2); aB3 = fma2_(wb, hB.y, aB3);
                }
                {
                    ull* g = sm.gred[ch];
                    g[(0 * 4 + c4) * 64 + rp] = aA0;
                    g[(1 * 4 + c4) * 64 + rp] = aA1;
                    g[(2 * 4 + c4) * 64 + rp] = aA2;
                    g[(3 * 4 + c4) * 64 + rp] = aA3;
                    g[(4 * 4 + c4) * 64 + rp] = aB0;
                    g[(5 * 4 + c4) * 64 + rp] = aB1;
                    g[(6 * 4 + c4) * 64 + rp] = aB2;
                    g[(7 * 4 + c4) * 64 + rp] = aB3;
                }
                NB_SYNC(5, 256);       // all producers done reading hbuf + wrote gred
                if (tid == 0 && s < T_LEN - 1) {
                    MBAR_EXPECT_TX(fullL[ch][p], 7168);
#pragma unroll
                    for (int j = 0; j < 8; ++j)
                        MBAR_ARRIVE_CLUSTER(mapa_(goL[ch][p], (unsigned)j));
                }
                NB_ARRIVE(1 + ch, 512);                      // gred[ch] ready
            }
        }
    } else {
        // =================== CONSUMER (reduce/cell/comm) ===================
        const int ci = tid - 256;
        const int rp2 = ci & 63, m = ci >> 6;    // rows 2rp2,2rp2+1; batch pair m
        const int jE = 2 * rp2;
        const int rgE = ((jE >> 5) << 8) + (cr << 5) + (jE & 31);
        const float* px0 = xg + (size_t)(b0A + 2 * m) * G4H + rgE;      // batch 2m
        const float* px1 = px0 + G4H;                                    // batch 2m+1
        const int baseE = (m * 4) * 64 + rp2;
        const int baseO = ((4 + m) * 4) * 64 + rp2;
        const int u = ci >> 3, bb = ci & 7;       // cell role
        const int sb = ci >> 3, skq = ci & 7;     // h gmem store role (ci<64)
        unsigned phG[2] = {0, 0};

        for (int s = 0; s < T_LEN; ++s) {
            const int p = s & 1, q = p ^ 1;
            // prefetch xg for both chains (rows rgE, rgE+1 per batch)
            const size_t so = (size_t)s * B_SZ * G4H;
            float2 xa0 = *reinterpret_cast<const float2*>(&px0[so]);
            float2 xa1 = *reinterpret_cast<const float2*>(&px1[so]);
            float2 xb0 = *reinterpret_cast<const float2*>(&px0[so + 8 * G4H]);
            float2 xb1 = *reinterpret_cast<const float2*>(&px1[so + 8 * G4H]);

#pragma unroll
            for (int ch = 0; ch < 2; ++ch) {
                const float2 x0 = ch ? xb0 : xa0;
                const float2 x1 = ch ? xb1 : xa1;

                NB_SYNC(1 + ch, 512);                        // gred[ch] ready
                // reduce 4 k-chunks + xg, write gates
                {
                    const ull* g = sm.gred[ch];
                    ull vE = add2_(add2_(g[baseE], g[baseE + 64]),
                                   add2_(g[baseE + 128], g[baseE + 192]));
                    ull vO = add2_(add2_(g[baseO], g[baseO + 64]),
                                   add2_(g[baseO + 128], g[baseO + 192]));
                    vE = add2_(vE, pk2(x0.x, x1.x));
                    vO = add2_(vO, pk2(x0.y, x1.y));
                    float lo, hi;
                    upk2(vE, lo, hi);
                    sm.gfull[2 * m][jE] = lo; sm.gfull[2 * m + 1][jE] = hi;
                    upk2(vO, lo, hi);
                    sm.gfull[2 * m][jE + 1] = lo; sm.gfull[2 * m + 1][jE + 1] = hi;
                }
                NB_SYNC(6, 256);
                // LSTM cell
                {
                    float gi = sm.gfull[bb][u];
                    float gf = sm.gfull[bb][32 + u];
                    float gg = sm.gfull[bb][64 + u];
                    float go = sm.gfull[bb][96 + u];
                    float cc = sgm(gf) * c_reg[ch] + sgm(gi) * tanh_(gg);
                    c_reg[ch] = cc;
                    float hv = sgm(go) * tanh_(cc);
                    sm.hstage[ch][p][ci] = hv;
                    sm.hbuf[ch][q][cr * 32 + u][bb] = hv;    // self-slice
                }
                NB_SYNC(7, 256);
                // messenger: push own slice to 7 peers
                if (ci == 0 && s < T_LEN - 1) {
                    asm volatile("fence.proxy.async.shared::cta;" ::: "memory");
                    MBAR_WAIT(goL[ch][q], (phG[ch] >> q) & 1);
                    phG[ch] ^= (1u << q);
                    const unsigned src = smem_u32(&sm.hstage[ch][p][0]);
#pragma unroll
                    for (int j = 0; j < 8; ++j) {
                        if (j == cr) continue;
                        unsigned dst = mapa_(dstL[ch][q], (unsigned)j);
                        unsigned mb = mapa_(fullL[ch][q], (unsigned)j);
                        BULK_S2S(dst, src, 1024u, mb);
                    }
                }
                // h to gmem for score GEMM
                if (ci < 64) {
                    float4 o;
                    o.x = sm.hstage[ch][p][(skq * 4 + 0) * 8 + sb];
                    o.y = sm.hstage[ch][p][(skq * 4 + 1) * 8 + sb];
                    o.z = sm.hstage[ch][p][(skq * 4 + 2) * 8 + sb];
                    o.w = sm.hstage[ch][p][(skq * 4 + 3) * 8 + sb];
                    int tOut = dir ? (T_LEN - 1 - s) : s;
                    *reinterpret_cast<float4*>(
                        &g_h[(size_t)tOut * B_SZ + b0A + ch * 8 + sb]
                            [dir * H_DIM + cr * 32 + skq * 4]) = o;
                }
                NB_ARRIVE(3 + ch, 512);                      // gred free + h self ok
            }
        }
    }

    CLUSTER_SYNC();
    if (tid == 0) {
#pragma unroll
        for (int ch = 0; ch < 2; ++ch) {
            MBAR_INVAL(fullL[ch][0]); MBAR_INVAL(fullL[ch][1]);
            MBAR_INVAL(goL[ch][0]);   MBAR_INVAL(goL[ch][1]);
        }
    }
}

// =====================================================================
// Kernel S: emission scores GEMM (R7 version).
// =====================================================================
__global__ void __launch_bounds__(256) kS(
    const float* __restrict__ Wlin, const float* __restrict__ blin)
{
    __shared__ float As[32][132];
    __shared__ float Bs[32][68];

    const int tid = threadIdx.x;
    const int mBase = blockIdx.x * 128;

    const int ty = tid >> 4;
    const int tx = tid & 15;

    ull acc[4][4];
#pragma unroll
    for (int m = 0; m < 4; m++)
#pragma unroll
        for (int j = 0; j < 4; j++) acc[m][j] = 0ull;

    const int arow = tid >> 3, akq = tid & 7;
    const int bn = tid >> 2, bkq = tid & 3;

    float4 pa[4], pb[2];
#pragma unroll
    for (int rr = 0; rr < 4; ++rr)
        pa[rr] = *reinterpret_cast<const float4*>(&g_h[mBase + arow + rr * 32][akq * 4]);
#pragma unroll
    for (int hh = 0; hh < 2; ++hh)
        pb[hh] = *reinterpret_cast<const float4*>(
            &Wlin[(size_t)bn * (2 * H_DIM) + bkq * 8 + hh * 4]);

    for (int kt = 0; kt < 16; ++kt) {
#pragma unroll
        for (int rr = 0; rr < 4; ++rr) {
            int r = arow + rr * 32;
            As[akq * 4 + 0][r] = pa[rr].x; As[akq * 4 + 1][r] = pa[rr].y;
            As[akq * 4 + 2][r] = pa[rr].z; As[akq * 4 + 3][r] = pa[rr].w;
        }
#pragma unroll
        for (int hh = 0; hh < 2; ++hh) {
            Bs[bkq * 8 + hh * 4 + 0][bn] = pb[hh].x; Bs[bkq * 8 + hh * 4 + 1][bn] = pb[hh].y;
            Bs[bkq * 8 + hh * 4 + 2][bn] = pb[hh].z; Bs[bkq * 8 + hh * 4 + 3][bn] = pb[hh].w;
        }
        __syncthreads();

        if (kt < 15) {
            const int kn = (kt + 1) * 32;
#pragma unroll
            for (int rr = 0; rr < 4; ++rr)
                pa[rr] = *reinterpret_cast<const float4*>(
                    &g_h[mBase + arow + rr * 32][kn + akq * 4]);
#pragma unroll
            for (int hh = 0; hh < 2; ++hh)
                pb[hh] = *reinterpret_cast<const float4*>(
                    &Wlin[(size_t)bn * (2 * H_DIM) + kn + bkq * 8 + hh * 4]);
        }

#pragma unroll 8
        for (int k = 0; k < 32; ++k) {
            float4 a0 = *reinterpret_cast<const float4*>(&As[k][ty * 8]);
            float4 a1 = *reinterpret_cast<const float4*>(&As[k][ty * 8 + 4]);
            float4 b4 = *reinterpret_cast<const float4*>(&Bs[k][tx * 4]);
            ull ap[4] = {pk2(a0.x, a0.y), pk2(a0.z, a0.w), pk2(a1.x, a1.y), pk2(a1.z, a1.w)};
            ull bd[4] = {pk2(b4.x, b4.x), pk2(b4.y, b4.y), pk2(b4.z, b4.z), pk2(b4.w, b4.w)};
#pragma unroll
            for (int m = 0; m < 4; ++m)
#pragma unroll
                for (int j = 0; j < 4; ++j)
                    acc[m][j] = fma2_(ap[m], bd[j], acc[m][j]);
        }
        __syncthreads();
    }

    const int n0 = tx * 4;
    float bias[4];
#pragma unroll
    for (int j = 0; j < 4; ++j) bias[j] = blin[n0 + j];
#pragma unroll
    for (int m = 0; m < 4; ++m) {
        float lo[4], hi[4];
#pragma unroll
        for (int j = 0; j < 4; ++j) upk2(acc[m][j], lo[j], hi[j]);
        int row0 = mBase + ty * 8 + 2 * m;
#pragma unroll
        for (int r = 0; r < 2; ++r) {
            const float* src = r ? hi : lo;
            float4 o = make_float4(src[0] + bias[0], src[1] + bias[1],
                                   src[2] + bias[2], src[3] + bias[3]);
            *reinterpret_cast<float4*>(&g_sc[row0 + r][n0]) = o;
        }
    }
}

// =====================================================================
// Kernel C: Viterbi DP + backtrace (R7 version).
// =====================================================================
__global__ void __launch_bounds__(512) kC(
    const float* __restrict__ pw,
    const float* __restrict__ startv, const float* __restrict__ stopv,
    float* __restrict__ out)
{
    __shared__ float delta[2][64];
    __shared__ float fin[64];
    __shared__ unsigned char bp[T_LEN - 1][64];

    const int b = blockIdx.x;
    const int tid = threadIdx.x;
    const int s = tid >> 3;      // state 0..63
    const int p = tid & 7;       // part 0..7

    float Pr[8];
#pragma unroll
    for (int i = 0; i < 8; ++i) Pr[i] = pw[(p * 8 + i) * 64 + s];

    if (p == 0) delta[0][s] = startv[s] + g_sc[b][s];
    __syncthreads();

    float scA = g_sc[(size_t)1 * B_SZ + b][s];
    float scB = g_sc[(size_t)2 * B_SZ + b][s];
    for (int t = 1; t < T_LEN; ++t) {
        const int pp = (t - 1) & 1, qq = t & 1;
        float4 d0 = *reinterpret_cast<const float4*>(&delta[pp][p * 8]);
        float4 d1 = *reinterpret_cast<const float4*>(&delta[pp][p * 8 + 4]);
        float dv[8] = {d0.x, d0.y, d0.z, d0.w, d1.x, d1.y, d1.z, d1.w};

        float best = dv[0] + Pr[0];
        int bi = p * 8;
#pragma unroll
        for (int i = 1; i < 8; ++i) {
            float v = dv[i] + Pr[i];
            if (v > best) { best = v; bi = p * 8 + i; }
        }
#pragma unroll
        for (int off = 1; off < 8; off <<= 1) {
            float ov = __shfl_xor_sync(0xffffffffu, best, off);
            int oi = __shfl_xor_sync(0xffffffffu, bi, off);
            if (ov > best || (ov == best && oi < bi)) { best = ov; bi = oi; }
        }

        const float sc = scA;
        scA = scB;
        if (t + 2 < T_LEN) scB = g_sc[(size_t)(t + 2) * B_SZ + b][s];

        if (p == 0) {
            bp[t - 1][s] = (unsigned char)bi;
            delta[qq][s] = best + sc;
        }
        __syncthreads();
    }

    if (p == 0) fin[s] = delta[(T_LEN - 1) & 1][s] + stopv[s];
    __syncthreads();

    if (tid == 0) {
        float best = fin[0]; int bi0 = 0;
        for (int i = 1; i < 64; ++i) if (fin[i] > best) { best = fin[i]; bi0 = i; }
        out[b] = best;
        int st = bi0;
        out[64 + (size_t)(T_LEN - 1) * B_SZ + b] = (float)st;
        for (int tt = T_LEN - 2; tt >= 0; --tt) {
            st = bp[tt][st];
            out[64 + (size_t)tt * B_SZ + b] = (float)st;
        }
    }
}

// =====================================================================
extern "C" void kernel_launch(void* const* d_in, const int* in_sizes, int n_in,
                              void* d_out, int out_size)
{
    const int*   obs  = (const int*)  d_in[0];
    const float* h0   = (const float*)d_in[1];
    const float* c0   = (const float*)d_in[2];
    const float* emb  = (const float*)d_in[3];
    const float* WihF = (const float*)d_in[4];
    const float* WhhF = (const float*)d_in[5];
    const float* bihF = (const float*)d_in[6];
    const float* bhhF = (const float*)d_in[7];
    const float* WihB = (const float*)d_in[8];
    const float* WhhB = (const float*)d_in[9];
    const float* bihB = (const float*)d_in[10];
    const float* bhhB = (const float*)d_in[11];
    const float* Wlin = (const float*)d_in[12];
    const float* blin = (const float*)d_in[13];
    const float* pw   = (const float*)d_in[14];
    const float* stv  = (const float*)d_in[15];
    const float* spv  = (const float*)d_in[16];
    float* out = (float*)d_out;

    const int smemB = (int)sizeof(SmemB);
    cudaFuncSetAttribute(kB, cudaFuncAttributeMaxDynamicSharedMemorySize, smemB);

    kA<<<dim3(256, 32), 256>>>(obs, emb, WihF, WihB, bihF, bhhF, bihB, bhhB);
    kB<<<64, 512, smemB>>>(WhhF, WhhB, h0, c0);
    kS<<<256, 256>>>(Wlin, blin);
    kC<<<64, 512>>>(pw, stv, spv, out);
}